// round 10
// baseline (speedup 1.0000x reference)
#include <cuda_runtime.h>
#include <cuda_bf16.h>
#include <cfloat>
#include <cstdint>

// ---------------------------------------------------------------------------
// Problem constants
//   skip   [256,343,384]  x_up [256,343,384]  pos_embed [256,343,384]
//   mask   [64,343,343]   kv_w [384,768] kv_b [768]
//   proj_w [384,384] proj_b [384] logit_scale [12,1,1] rpb_table [2197,12]
//   out    [256,343,384] fp32
// ---------------------------------------------------------------------------
#define B_   256
#define NN   343
#define CC   384
#define HH   12
#define DD   32
#define NW   64
#define MROWS (B_*NN)          // 87808

// Scratch (device globals; allocation inside kernel_launch is forbidden)
#define QKV_ELEMS (B_*HH*NN*DD)   // 33,718,272
__device__ float g_qn[QKV_ELEMS];      // normalized+scaled q, [b,h,n,d]
__device__ float g_k [QKV_ELEMS];      // k then normalized in place
__device__ float g_v [QKV_ELEMS];      // v
__device__ float g_attout[B_*NN*CC];   // attention output, [b,n,C]

// ---------------------------------------------------------------------------
// Kernel 1: q normalize + logit-scale fold.  One warp per (b,n,h) row of 32.
// ---------------------------------------------------------------------------
__global__ void qnorm_kernel(const float* __restrict__ x_up,
                             const float* __restrict__ logit_scale) {
    int gid  = blockIdx.x * 8 + (threadIdx.x >> 5);   // row id
    int lane = threadIdx.x & 31;
    int b = gid / (NN*HH);
    int r = gid - b*(NN*HH);
    int n = r / HH;
    int h = r - n*HH;
    float v = x_up[((size_t)b*NN + n)*CC + h*DD + lane];
    float ss = v*v;
    #pragma unroll
    for (int o = 16; o; o >>= 1) ss += __shfl_xor_sync(0xffffffffu, ss, o);
    float scale = __expf(fminf(logit_scale[h], 4.6051702f)); // ln(100)
    float qn = v / fmaxf(sqrtf(ss), 1e-12f) * scale;
    g_qn[(((size_t)b*HH + h)*NN + n)*DD + lane] = qn;
}

// ---------------------------------------------------------------------------
// Kernel 3: k row normalize in place (layout already [b,h,n,32])
// ---------------------------------------------------------------------------
__global__ void knorm_kernel() {
    int row  = blockIdx.x * 8 + (threadIdx.x >> 5);
    int lane = threadIdx.x & 31;
    float v = g_k[(size_t)row*DD + lane];
    float ss = v*v;
    #pragma unroll
    for (int o = 16; o; o >>= 1) ss += __shfl_xor_sync(0xffffffffu, ss, o);
    g_k[(size_t)row*DD + lane] = v / fmaxf(sqrtf(ss), 1e-12f);
}

// ---------------------------------------------------------------------------
// Kernel 2: kv GEMM 87808x768x384, epilogue scatters to g_k / g_v [b,h,n,d]
// BM=64 BN=64 BK=16, 256 threads, 4x4 micro-tile.
// ---------------------------------------------------------------------------
#define BM 64
#define BN 64
#define BK 16

__global__ __launch_bounds__(256) void kv_gemm_kernel(
    const float* __restrict__ A,      // skip [87808,384]
    const float* __restrict__ Bw,     // kv_w [384,768]
    const float* __restrict__ bias)   // kv_b [768]
{
    __shared__ float As[BK][BM+4];
    __shared__ float Bs[BK][BN+4];
    int tid = threadIdx.x;
    int tx = tid & 15, ty = tid >> 4;
    int m0 = blockIdx.y * BM, n0 = blockIdx.x * BN;
    int ar = tid >> 2, ak = (tid & 3) * 4;    // A tile: 64 rows x 16 k
    int br = tid >> 4, bc = (tid & 15) * 4;   // B tile: 16 rows x 64 n
    float acc[4][4] = {};
    for (int k0 = 0; k0 < CC; k0 += BK) {
        float4 a4 = *(const float4*)&A[(size_t)(m0 + ar)*CC + k0 + ak];
        As[ak+0][ar] = a4.x; As[ak+1][ar] = a4.y;
        As[ak+2][ar] = a4.z; As[ak+3][ar] = a4.w;
        *(float4*)&Bs[br][bc] = *(const float4*)&Bw[(size_t)(k0 + br)*768 + n0 + bc];
        __syncthreads();
        #pragma unroll
        for (int kk = 0; kk < BK; kk++) {
            float4 av = *(float4*)&As[kk][ty*4];
            float4 bv = *(float4*)&Bs[kk][tx*4];
            float a_[4] = {av.x, av.y, av.z, av.w};
            float b_[4] = {bv.x, bv.y, bv.z, bv.w};
            #pragma unroll
            for (int i = 0; i < 4; i++)
                #pragma unroll
                for (int j = 0; j < 4; j++)
                    acc[i][j] = fmaf(a_[i], b_[j], acc[i][j]);
        }
        __syncthreads();
    }
    #pragma unroll
    for (int i = 0; i < 4; i++) {
        int m = m0 + ty*4 + i;
        int bb = m / NN, n = m - bb*NN;
        #pragma unroll
        for (int j = 0; j < 4; j++) {
            int col = n0 + tx*4 + j;
            float val = acc[i][j] + bias[col];
            int sel = (col >= CC);
            int cc  = col - (sel ? CC : 0);
            int hh  = cc >> 5, dd = cc & 31;
            float* dst = sel ? g_v : g_k;
            dst[(((size_t)bb*HH + hh)*NN + n)*DD + dd] = val;
        }
    }
}

// ---------------------------------------------------------------------------
// Kernel 5: proj GEMM 87808x384x384, A = g_attout + pos_embed (fused)
// ---------------------------------------------------------------------------
__global__ __launch_bounds__(256) void proj_gemm_kernel(
    const float* __restrict__ pos,    // pos_embed [87808,384]
    const float* __restrict__ Bw,     // proj_w [384,384]
    const float* __restrict__ bias,   // proj_b [384]
    float* __restrict__ out)
{
    __shared__ float As[BK][BM+4];
    __shared__ float Bs[BK][BN+4];
    int tid = threadIdx.x;
    int tx = tid & 15, ty = tid >> 4;
    int m0 = blockIdx.y * BM, n0 = blockIdx.x * BN;
    int ar = tid >> 2, ak = (tid & 3) * 4;
    int br = tid >> 4, bc = (tid & 15) * 4;
    float acc[4][4] = {};
    for (int k0 = 0; k0 < CC; k0 += BK) {
        size_t aidx = (size_t)(m0 + ar)*CC + k0 + ak;
        float4 a4 = *(const float4*)&g_attout[aidx];
        float4 p4 = *(const float4*)&pos[aidx];
        As[ak+0][ar] = a4.x + p4.x; As[ak+1][ar] = a4.y + p4.y;
        As[ak+2][ar] = a4.z + p4.z; As[ak+3][ar] = a4.w + p4.w;
        *(float4*)&Bs[br][bc] = *(const float4*)&Bw[(size_t)(k0 + br)*CC + n0 + bc];
        __syncthreads();
        #pragma unroll
        for (int kk = 0; kk < BK; kk++) {
            float4 av = *(float4*)&As[kk][ty*4];
            float4 bv = *(float4*)&Bs[kk][tx*4];
            float a_[4] = {av.x, av.y, av.z, av.w};
            float b_[4] = {bv.x, bv.y, bv.z, bv.w};
            #pragma unroll
            for (int i = 0; i < 4; i++)
                #pragma unroll
                for (int j = 0; j < 4; j++)
                    acc[i][j] = fmaf(a_[i], b_[j], acc[i][j]);
        }
        __syncthreads();
    }
    #pragma unroll
    for (int i = 0; i < 4; i++) {
        int m = m0 + ty*4 + i;
        #pragma unroll
        for (int j = 0; j < 4; j++) {
            int col = n0 + tx*4 + j;
            out[(size_t)m*CC + col] = acc[i][j] + bias[col];
        }
    }
}

// ---------------------------------------------------------------------------
// Kernel 4: fused attention. One block per (b,h). 256 threads (8 warps).
// kn/v staged in smem with 36-float row pitch (conflict-free LDS.128).
// Bias: rpi(i,j) = code(i)-code(j)+204, code = 20*s+13*h+w, LUT of 409 floats.
// 2-row register blocking per warp; AV accumulated in registers, reduced via
// 33-pad smem transpose.
// ---------------------------------------------------------------------------
#define SM_KN   0
#define SM_V    12348              // 343*36
#define SM_BIAS 24696
#define SM_CODE 25108              // ints
#define SM_QROW 25452              // [8 warps][2 rows][32]
#define SM_RED  25964              // [8 warps][32*33]
#define ATTN_SMEM_FLOATS (25964 + 8448)
#define ATTN_SMEM_BYTES  (ATTN_SMEM_FLOATS * 4)

__global__ __launch_bounds__(256, 1) void attn_kernel(
    const float* __restrict__ mask,   // [64,343,343]
    const float* __restrict__ rpb)    // [2197,12]
{
    extern __shared__ float sm[];
    float* kn_s   = sm + SM_KN;
    float* v_s    = sm + SM_V;
    float* bias_s = sm + SM_BIAS;
    int*   code_s = (int*)(sm + SM_CODE);
    float* qrow_s = sm + SM_QROW;
    float* red_s  = sm + SM_RED;

    int bh = blockIdx.x;
    int b  = bh / HH, h = bh - b*HH;
    int tid = threadIdx.x, warp = tid >> 5, lane = tid & 31;

    const float* kbase = g_k  + ((size_t)(b*HH + h))*NN*DD;
    const float* vbase = g_v  + ((size_t)(b*HH + h))*NN*DD;
    const float* qbase = g_qn + ((size_t)(b*HH + h))*NN*DD;

    for (int t = tid; t < NN*8; t += 256) {
        int m = t >> 3, c4 = (t & 7) * 4;
        *(float4*)&kn_s[m*36 + c4] = *(const float4*)&kbase[m*DD + c4];
        *(float4*)&v_s [m*36 + c4] = *(const float4*)&vbase[m*DD + c4];
    }
    for (int t = tid; t < 409; t += 256) bias_s[t] = rpb[t*HH + h];
    for (int t = tid; t < NN; t += 256)
        code_s[t] = 20*(t/49) + 13*((t/7)%7) + (t%7);
    __syncthreads();

    const float* maskw = mask + (size_t)(b & 63)*NN*NN;

    for (int i0 = 0; i0 < NN; i0 += 16) {
        int iA = i0 + warp;
        int iB = i0 + 8 + warp;
        bool aA = iA < NN, aB = iB < NN;
        if (aA) qrow_s[(warp*2 + 0)*32 + lane] = qbase[iA*DD + lane];
        if (aB) qrow_s[(warp*2 + 1)*32 + lane] = qbase[iB*DD + lane];
        __syncwarp();
        const float4* q0 = (const float4*)&qrow_s[(warp*2 + 0)*32];
        const float4* q1 = (const float4*)&qrow_s[(warp*2 + 1)*32];

        int codeA = aA ? code_s[iA] : 0;
        int codeB = aB ? code_s[iB] : 0;
        const float* mrowA = maskw + (size_t)iA*NN;
        const float* mrowB = maskw + (size_t)iB*NN;

        float sA[11], sB[11];
        float mxA = -FLT_MAX, mxB = -FLT_MAX;
        #pragma unroll
        for (int c = 0; c < 11; c++) {
            int m = lane + 32*c;
            float sa = -FLT_MAX, sb = -FLT_MAX;
            if (m < NN) {
                const float4* kp = (const float4*)&kn_s[m*36];
                float dA = 0.f, dB = 0.f;
                #pragma unroll
                for (int k4 = 0; k4 < 8; k4++) {
                    float4 kv4 = kp[k4];
                    float4 qa  = q0[k4];
                    float4 qb  = q1[k4];
                    dA = fmaf(qa.x, kv4.x, dA); dA = fmaf(qa.y, kv4.y, dA);
                    dA = fmaf(qa.z, kv4.z, dA); dA = fmaf(qa.w, kv4.w, dA);
                    dB = fmaf(qb.x, kv4.x, dB); dB = fmaf(qb.y, kv4.y, dB);
                    dB = fmaf(qb.z, kv4.z, dB); dB = fmaf(qb.w, kv4.w, dB);
                }
                int cm = code_s[m];
                if (aA) sa = dA + bias_s[codeA - cm + 204] + mrowA[m];
                if (aB) sb = dB + bias_s[codeB - cm + 204] + mrowB[m];
            }
            sA[c] = sa; sB[c] = sb;
            mxA = fmaxf(mxA, sa); mxB = fmaxf(mxB, sb);
        }
        #pragma unroll
        for (int o = 16; o; o >>= 1) {
            mxA = fmaxf(mxA, __shfl_xor_sync(0xffffffffu, mxA, o));
            mxB = fmaxf(mxB, __shfl_xor_sync(0xffffffffu, mxB, o));
        }
        float sumA = 0.f, sumB = 0.f;
        #pragma unroll
        for (int c = 0; c < 11; c++) {
            float pa = __expf(sA[c] - mxA);
            float pb = __expf(sB[c] - mxB);
            if (lane + 32*c >= NN) { pa = 0.f; pb = 0.f; }
            sA[c] = pa; sB[c] = pb;
            sumA += pa; sumB += pb;
        }
        #pragma unroll
        for (int o = 16; o; o >>= 1) {
            sumA += __shfl_xor_sync(0xffffffffu, sumA, o);
            sumB += __shfl_xor_sync(0xffffffffu, sumB, o);
        }
        float invA = 1.0f / sumA, invB = 1.0f / sumB;

        // AV in registers
        float accA[32], accB[32];
        #pragma unroll
        for (int d = 0; d < 32; d++) { accA[d] = 0.f; accB[d] = 0.f; }
        #pragma unroll
        for (int c = 0; c < 11; c++) {
            int m = lane + 32*c;
            if (m < NN) {
                const float4* vp = (const float4*)&v_s[m*36];
                float pa = sA[c], pb = sB[c];
                #pragma unroll
                for (int k4 = 0; k4 < 8; k4++) {
                    float4 vv = vp[k4];
                    accA[k4*4+0] = fmaf(pa, vv.x, accA[k4*4+0]);
                    accA[k4*4+1] = fmaf(pa, vv.y, accA[k4*4+1]);
                    accA[k4*4+2] = fmaf(pa, vv.z, accA[k4*4+2]);
                    accA[k4*4+3] = fmaf(pa, vv.w, accA[k4*4+3]);
                    accB[k4*4+0] = fmaf(pb, vv.x, accB[k4*4+0]);
                    accB[k4*4+1] = fmaf(pb, vv.y, accB[k4*4+1]);
                    accB[k4*4+2] = fmaf(pb, vv.z, accB[k4*4+2]);
                    accB[k4*4+3] = fmaf(pb, vv.w, accB[k4*4+3]);
                }
            }
        }
        // cross-lane transpose-reduce (row A)
        float* red = red_s + warp*1056;
        #pragma unroll
        for (int d = 0; d < 32; d++) red[lane*33 + d] = accA[d];
        __syncwarp();
        float totA = 0.f;
        #pragma unroll
        for (int L = 0; L < 32; L++) totA += red[L*33 + lane];
        if (aA) g_attout[((size_t)b*NN + iA)*CC + h*DD + lane] = totA * invA;
        __syncwarp();
        // row B
        #pragma unroll
        for (int d = 0; d < 32; d++) red[lane*33 + d] = accB[d];
        __syncwarp();
        float totB = 0.f;
        #pragma unroll
        for (int L = 0; L < 32; L++) totB += red[L*33 + lane];
        if (aB) g_attout[((size_t)b*NN + iB)*CC + h*DD + lane] = totB * invB;
        __syncwarp();
    }
}

// ---------------------------------------------------------------------------
extern "C" void kernel_launch(void* const* d_in, const int* in_sizes, int n_in,
                              void* d_out, int out_size) {
    const float* skip   = (const float*)d_in[0];
    const float* x_up   = (const float*)d_in[1];
    const float* pos    = (const float*)d_in[2];
    const float* mask   = (const float*)d_in[3];
    const float* kv_w   = (const float*)d_in[4];
    const float* kv_b   = (const float*)d_in[5];
    const float* proj_w = (const float*)d_in[6];
    const float* proj_b = (const float*)d_in[7];
    const float* lscale = (const float*)d_in[8];
    const float* rpb    = (const float*)d_in[9];
    float* out = (float*)d_out;

    cudaFuncSetAttribute(attn_kernel,
                         cudaFuncAttributeMaxDynamicSharedMemorySize,
                         ATTN_SMEM_BYTES);

    // 1) q normalize + scale fold:  256*343*12 rows / 8 warps per block
    qnorm_kernel<<<131712, 256>>>(x_up, lscale);
    // 2) kv GEMM + scatter: grid (768/64, 87808/64)
    kv_gemm_kernel<<<dim3(12, 1372), 256>>>(skip, kv_w, kv_b);
    // 3) k normalize in place
    knorm_kernel<<<131712, 256>>>();
    // 4) attention: one block per (b,h)
    attn_kernel<<<B_*HH, 256, ATTN_SMEM_BYTES>>>(mask, rpb);
    // 5) projection GEMM fused with pos_embed add
    proj_gemm_kernel<<<dim3(6, 1372), 256>>>(pos, proj_w, proj_b, out);
}

// round 14
// speedup vs baseline: 1.2989x; 1.2989x over previous
#include <cuda_runtime.h>
#include <cuda_bf16.h>
#include <cfloat>
#include <cstdint>

// ---------------------------------------------------------------------------
// Problem constants
// ---------------------------------------------------------------------------
#define B_   256
#define NN   343
#define CC   384
#define HH   12
#define DD   32
#define MROWS (B_*NN)          // 87808
#define NKV  768               // kv out cols

// ---------------------------------------------------------------------------
// Scratch (device globals)
// ---------------------------------------------------------------------------
#define QKV_ELEMS (B_*HH*NN*DD)   // 33,718,272
__device__ float g_qn[QKV_ELEMS];
__device__ float g_k [QKV_ELEMS];
__device__ float g_v [QKV_ELEMS];
__device__ float g_attout[B_*NN*CC];
// bf16 hi/lo splits for tensor-core GEMMs
__device__ __nv_bfloat16 g_skip_hi[(size_t)MROWS*CC];
__device__ __nv_bfloat16 g_skip_lo[(size_t)MROWS*CC];
__device__ __nv_bfloat16 g_ain_hi [(size_t)MROWS*CC];
__device__ __nv_bfloat16 g_ain_lo [(size_t)MROWS*CC];
__device__ __nv_bfloat16 g_kvw_hi[NKV*CC];   // [n][k] K-major (transposed)
__device__ __nv_bfloat16 g_kvw_lo[NKV*CC];
__device__ __nv_bfloat16 g_pw_hi [CC*CC];
__device__ __nv_bfloat16 g_pw_lo [CC*CC];

// ---------------------------------------------------------------------------
// mma.sync helper (base-arch PTX: works under compute_103, no 'a' features)
// ---------------------------------------------------------------------------
__device__ __forceinline__ void mma16816(float* c, const uint32_t* a, const uint32_t* b) {
    asm volatile(
        "mma.sync.aligned.m16n8k16.row.col.f32.bf16.bf16.f32 "
        "{%0,%1,%2,%3}, {%4,%5,%6,%7}, {%8,%9}, {%0,%1,%2,%3};"
        : "+f"(c[0]), "+f"(c[1]), "+f"(c[2]), "+f"(c[3])
        : "r"(a[0]), "r"(a[1]), "r"(a[2]), "r"(a[3]), "r"(b[0]), "r"(b[1]));
}

// ---------------------------------------------------------------------------
// Prep kernels: fp32 -> bf16 hi/lo splits
// ---------------------------------------------------------------------------
__global__ void prep_split(const float* __restrict__ src,
                           __nv_bfloat16* __restrict__ hi, __nv_bfloat16* __restrict__ lo) {
    size_t i = (size_t)blockIdx.x * 256 + threadIdx.x;
    float x = src[i];
    __nv_bfloat16 h = __float2bfloat16(x);
    hi[i] = h;
    lo[i] = __float2bfloat16(x - __bfloat162float(h));
}
__global__ void prep_add_split(const float* __restrict__ a, const float* __restrict__ b,
                               __nv_bfloat16* __restrict__ hi, __nv_bfloat16* __restrict__ lo) {
    size_t i = (size_t)blockIdx.x * 256 + threadIdx.x;
    float x = a[i] + b[i];
    __nv_bfloat16 h = __float2bfloat16(x);
    hi[i] = h;
    lo[i] = __float2bfloat16(x - __bfloat162float(h));
}
// W [K,Nw] row-major -> out [n][k] K-major transposed split
__global__ void prep_w_split(const float* __restrict__ W, int Nw,
                             __nv_bfloat16* __restrict__ hi, __nv_bfloat16* __restrict__ lo) {
    int i = blockIdx.x * 256 + threadIdx.x;   // i = n*CC + k
    int n = i / CC, k = i - n * CC;
    float x = W[(size_t)k * Nw + n];
    __nv_bfloat16 h = __float2bfloat16(x);
    hi[i] = h;
    lo[i] = __float2bfloat16(x - __bfloat162float(h));
}

// ---------------------------------------------------------------------------
// Kernel 1: q normalize + logit-scale fold
// ---------------------------------------------------------------------------
__global__ void qnorm_kernel(const float* __restrict__ x_up,
                             const float* __restrict__ logit_scale) {
    int gid  = blockIdx.x * 8 + (threadIdx.x >> 5);
    int lane = threadIdx.x & 31;
    int b = gid / (NN*HH);
    int r = gid - b*(NN*HH);
    int n = r / HH;
    int h = r - n*HH;
    float v = x_up[((size_t)b*NN + n)*CC + h*DD + lane];
    float ss = v*v;
    #pragma unroll
    for (int o = 16; o; o >>= 1) ss += __shfl_xor_sync(0xffffffffu, ss, o);
    float scale = __expf(fminf(logit_scale[h], 4.6051702f));
    float qn = v / fmaxf(sqrtf(ss), 1e-12f) * scale;
    g_qn[(((size_t)b*HH + h)*NN + n)*DD + lane] = qn;
}

// ---------------------------------------------------------------------------
// Kernel 3: k row normalize in place
// ---------------------------------------------------------------------------
__global__ void knorm_kernel() {
    int row  = blockIdx.x * 8 + (threadIdx.x >> 5);
    int lane = threadIdx.x & 31;
    float v = g_k[(size_t)row*DD + lane];
    float ss = v*v;
    #pragma unroll
    for (int o = 16; o; o >>= 1) ss += __shfl_xor_sync(0xffffffffu, ss, o);
    g_k[(size_t)row*DD + lane] = v / fmaxf(sqrtf(ss), 1e-12f);
}

// ---------------------------------------------------------------------------
// HMMA GEMM core: C[128,128] = A(hi+lo) @ B(hi+lo)^T, K=384 in 6 chunks of 64.
// smem tiles 128 rows x 72 bf16 pitch (36 words: frag LDS lands on 32 distinct
// banks since row*36 mod 32 = row*4, spacing 4 >= tig range).
// 8 warps = 2x4; warp tile 64x32 = 4x4 m16n8k16 atoms.
// 3 passes: Ahi*Bhi + Ahi*Blo + Alo*Bhi (fp32 accum, ~2^-16 rel error).
// ---------------------------------------------------------------------------
#define SWP   36                       // smem row pitch in 32-bit words
#define TILE_BYTES (128*SWP*4)         // 18432
#define GEMM_SMEM (4*TILE_BYTES)       // 73728
#define KCH   64
#define NCH   (CC/KCH)                 // 6

__device__ __forceinline__ void stage64(uint4* sm_tile, const __nv_bfloat16* g,
                                        int row0, int k0, int tid) {
    #pragma unroll
    for (int i = 0; i < 4; i++) {
        int idx = i * 256 + tid;           // 1024 uint4 total
        int row = idx >> 3, seg = idx & 7; // 8 uint4 per 64-bf16 row
        sm_tile[row * (SWP/4) + seg] =
            *(const uint4*)(g + (size_t)(row0 + row) * CC + k0 + seg * 8);
    }
}

__device__ __forceinline__ void gemm_core(
    float (*acc)[4][4], char* smem, int m0, int n0,
    const __nv_bfloat16* gAhi, const __nv_bfloat16* gAlo,
    const __nv_bfloat16* gBhi, const __nv_bfloat16* gBlo)
{
    int tid = threadIdx.x, warp = tid >> 5, lane = tid & 31;
    int wm = warp >> 2, wn = warp & 3;
    int g = lane >> 2, tig = lane & 3;
    uint4* smA_hi = (uint4*)(smem);
    uint4* smA_lo = (uint4*)(smem + TILE_BYTES);
    uint4* smB_hi = (uint4*)(smem + 2*TILE_BYTES);
    uint4* smB_lo = (uint4*)(smem + 3*TILE_BYTES);
    const uint32_t* wAh = (const uint32_t*)smA_hi;
    const uint32_t* wAl = (const uint32_t*)smA_lo;
    const uint32_t* wBh = (const uint32_t*)smB_hi;
    const uint32_t* wBl = (const uint32_t*)smB_lo;

    for (int c = 0; c < NCH; c++) {
        __syncthreads();
        stage64(smA_hi, gAhi, m0, c*KCH, tid);
        stage64(smA_lo, gAlo, m0, c*KCH, tid);
        stage64(smB_hi, gBhi, n0, c*KCH, tid);
        stage64(smB_lo, gBlo, n0, c*KCH, tid);
        __syncthreads();
        #pragma unroll
        for (int ko = 0; ko < 4; ko++) {
            uint32_t ah[4][4], al[4][4], bh[4][2], bl[4][2];
            int wk = ko*8 + tig;
            #pragma unroll
            for (int ma = 0; ma < 4; ma++) {
                int r0 = (wm*64 + ma*16 + g) * SWP;
                int r8 = r0 + 8*SWP;
                ah[ma][0] = wAh[r0 + wk];     ah[ma][1] = wAh[r8 + wk];
                ah[ma][2] = wAh[r0 + wk + 4]; ah[ma][3] = wAh[r8 + wk + 4];
                al[ma][0] = wAl[r0 + wk];     al[ma][1] = wAl[r8 + wk];
                al[ma][2] = wAl[r0 + wk + 4]; al[ma][3] = wAl[r8 + wk + 4];
            }
            #pragma unroll
            for (int na = 0; na < 4; na++) {
                int r0 = (wn*32 + na*8 + g) * SWP;
                bh[na][0] = wBh[r0 + wk]; bh[na][1] = wBh[r0 + wk + 4];
                bl[na][0] = wBl[r0 + wk]; bl[na][1] = wBl[r0 + wk + 4];
            }
            #pragma unroll
            for (int ma = 0; ma < 4; ma++)
                #pragma unroll
                for (int na = 0; na < 4; na++) {
                    mma16816(acc[ma][na], ah[ma], bh[na]);
                    mma16816(acc[ma][na], ah[ma], bl[na]);
                    mma16816(acc[ma][na], al[ma], bh[na]);
                }
        }
    }
}

__global__ __launch_bounds__(256, 1) void kv_gemm_mma(const float* __restrict__ bias) {
    extern __shared__ char smem[];
    int n0 = blockIdx.x * 128, m0 = blockIdx.y * 128;
    float acc[4][4][4];
    #pragma unroll
    for (int i = 0; i < 4; i++)
        #pragma unroll
        for (int j = 0; j < 4; j++)
            #pragma unroll
            for (int k = 0; k < 4; k++) acc[i][j][k] = 0.f;

    gemm_core(acc, smem, m0, n0, g_skip_hi, g_skip_lo, g_kvw_hi, g_kvw_lo);

    int warp = threadIdx.x >> 5, lane = threadIdx.x & 31;
    int wm = warp >> 2, wn = warp & 3;
    int g = lane >> 2, tig = lane & 3;
    #pragma unroll
    for (int ma = 0; ma < 4; ma++) {
        #pragma unroll
        for (int na = 0; na < 4; na++) {
            int C0 = n0 + wn*32 + na*8 + tig*2;
            float b0 = bias[C0], b1 = bias[C0 + 1];
            int sel = (C0 >= CC);
            int cc = C0 - (sel ? CC : 0);
            int hh = cc >> 5, dd = cc & 31;
            float* base = sel ? g_v : g_k;
            #pragma unroll
            for (int rr = 0; rr < 2; rr++) {
                int R = m0 + wm*64 + ma*16 + g + rr*8;
                int bb = R / NN, n = R - bb*NN;
                float* dst = base + (((size_t)bb*HH + hh)*NN + n)*DD + dd;
                dst[0] = acc[ma][na][rr*2 + 0] + b0;
                dst[1] = acc[ma][na][rr*2 + 1] + b1;
            }
        }
    }
}

__global__ __launch_bounds__(256, 1) void proj_gemm_mma(const float* __restrict__ bias,
                                                        float* __restrict__ out) {
    extern __shared__ char smem[];
    int n0 = blockIdx.x * 128, m0 = blockIdx.y * 128;
    float acc[4][4][4];
    #pragma unroll
    for (int i = 0; i < 4; i++)
        #pragma unroll
        for (int j = 0; j < 4; j++)
            #pragma unroll
            for (int k = 0; k < 4; k++) acc[i][j][k] = 0.f;

    gemm_core(acc, smem, m0, n0, g_ain_hi, g_ain_lo, g_pw_hi, g_pw_lo);

    int warp = threadIdx.x >> 5, lane = threadIdx.x & 31;
    int wm = warp >> 2, wn = warp & 3;
    int g = lane >> 2, tig = lane & 3;
    #pragma unroll
    for (int ma = 0; ma < 4; ma++) {
        #pragma unroll
        for (int na = 0; na < 4; na++) {
            int C0 = n0 + wn*32 + na*8 + tig*2;
            float b0 = bias[C0], b1 = bias[C0 + 1];
            #pragma unroll
            for (int rr = 0; rr < 2; rr++) {
                int R = m0 + wm*64 + ma*16 + g + rr*8;
                float* dst = out + (size_t)R*CC + C0;
                dst[0] = acc[ma][na][rr*2 + 0] + b0;
                dst[1] = acc[ma][na][rr*2 + 1] + b1;
            }
        }
    }
}

// ---------------------------------------------------------------------------
// Kernel 4: fused attention (unchanged from passing baseline)
// ---------------------------------------------------------------------------
#define SM_KN   0
#define SM_V    12348
#define SM_BIAS 24696
#define SM_CODE 25108
#define SM_QROW 25452
#define SM_RED  25964
#define ATTN_SMEM_FLOATS (25964 + 8448)
#define ATTN_SMEM_BYTES  (ATTN_SMEM_FLOATS * 4)

__global__ __launch_bounds__(256, 1) void attn_kernel(
    const float* __restrict__ mask,
    const float* __restrict__ rpb)
{
    extern __shared__ float sm[];
    float* kn_s   = sm + SM_KN;
    float* v_s    = sm + SM_V;
    float* bias_s = sm + SM_BIAS;
    int*   code_s = (int*)(sm + SM_CODE);
    float* qrow_s = sm + SM_QROW;
    float* red_s  = sm + SM_RED;

    int bh = blockIdx.x;
    int b  = bh / HH, h = bh - b*HH;
    int tid = threadIdx.x, warp = tid >> 5, lane = tid & 31;

    const float* kbase = g_k  + ((size_t)(b*HH + h))*NN*DD;
    const float* vbase = g_v  + ((size_t)(b*HH + h))*NN*DD;
    const float* qbase = g_qn + ((size_t)(b*HH + h))*NN*DD;

    for (int t = tid; t < NN*8; t += 256) {
        int m = t >> 3, c4 = (t & 7) * 4;
        *(float4*)&kn_s[m*36 + c4] = *(const float4*)&kbase[m*DD + c4];
        *(float4*)&v_s [m*36 + c4] = *(const float4*)&vbase[m*DD + c4];
    }
    for (int t = tid; t < 409; t += 256) bias_s[t] = rpb[t*HH + h];
    for (int t = tid; t < NN; t += 256)
        code_s[t] = 20*(t/49) + 13*((t/7)%7) + (t%7);
    __syncthreads();

    const float* maskw = mask + (size_t)(b & 63)*NN*NN;

    for (int i0 = 0; i0 < NN; i0 += 16) {
        int iA = i0 + warp;
        int iB = i0 + 8 + warp;
        bool aA = iA < NN, aB = iB < NN;
        if (aA) qrow_s[(warp*2 + 0)*32 + lane] = qbase[iA*DD + lane];
        if (aB) qrow_s[(warp*2 + 1)*32 + lane] = qbase[iB*DD + lane];
        __syncwarp();
        const float4* q0 = (const float4*)&qrow_s[(warp*2 + 0)*32];
        const float4* q1 = (const float4*)&qrow_s[(warp*2 + 1)*32];

        int codeA = aA ? code_s[iA] : 0;
        int codeB = aB ? code_s[iB] : 0;
        const float* mrowA = maskw + (size_t)iA*NN;
        const float* mrowB = maskw + (size_t)iB*NN;

        float sA[11], sB[11];
        float mxA = -FLT_MAX, mxB = -FLT_MAX;
        #pragma unroll
        for (int c = 0; c < 11; c++) {
            int m = lane + 32*c;
            float sa = -FLT_MAX, sb = -FLT_MAX;
            if (m < NN) {
                const float4* kp = (const float4*)&kn_s[m*36];
                float dA = 0.f, dB = 0.f;
                #pragma unroll
                for (int k4 = 0; k4 < 8; k4++) {
                    float4 kv4 = kp[k4];
                    float4 qa  = q0[k4];
                    float4 qb  = q1[k4];
                    dA = fmaf(qa.x, kv4.x, dA); dA = fmaf(qa.y, kv4.y, dA);
                    dA = fmaf(qa.z, kv4.z, dA); dA = fmaf(qa.w, kv4.w, dA);
                    dB = fmaf(qb.x, kv4.x, dB); dB = fmaf(qb.y, kv4.y, dB);
                    dB = fmaf(qb.z, kv4.z, dB); dB = fmaf(qb.w, kv4.w, dB);
                }
                int cm = code_s[m];
                if (aA) sa = dA + bias_s[codeA - cm + 204] + mrowA[m];
                if (aB) sb = dB + bias_s[codeB - cm + 204] + mrowB[m];
            }
            sA[c] = sa; sB[c] = sb;
            mxA = fmaxf(mxA, sa); mxB = fmaxf(mxB, sb);
        }
        #pragma unroll
        for (int o = 16; o; o >>= 1) {
            mxA = fmaxf(mxA, __shfl_xor_sync(0xffffffffu, mxA, o));
            mxB = fmaxf(mxB, __shfl_xor_sync(0xffffffffu, mxB, o));
        }
        float sumA = 0.f, sumB = 0.f;
        #pragma unroll
        for (int c = 0; c < 11; c++) {
            float pa = __expf(sA[c] - mxA);
            float pb = __expf(sB[c] - mxB);
            if (lane + 32*c >= NN) { pa = 0.f; pb = 0.f; }
            sA[c] = pa; sB[c] = pb;
            sumA += pa; sumB += pb;
        }
        #pragma unroll
        for (int o = 16; o; o >>= 1) {
            sumA += __shfl_xor_sync(0xffffffffu, sumA, o);
            sumB += __shfl_xor_sync(0xffffffffu, sumB, o);
        }
        float invA = 1.0f / sumA, invB = 1.0f / sumB;

        float accA[32], accB[32];
        #pragma unroll
        for (int d = 0; d < 32; d++) { accA[d] = 0.f; accB[d] = 0.f; }
        #pragma unroll
        for (int c = 0; c < 11; c++) {
            int m = lane + 32*c;
            if (m < NN) {
                const float4* vp = (const float4*)&v_s[m*36];
                float pa = sA[c], pb = sB[c];
                #pragma unroll
                for (int k4 = 0; k4 < 8; k4++) {
                    float4 vv = vp[k4];
                    accA[k4*4+0] = fmaf(pa, vv.x, accA[k4*4+0]);
                    accA[k4*4+1] = fmaf(pa, vv.y, accA[k4*4+1]);
                    accA[k4*4+2] = fmaf(pa, vv.z, accA[k4*4+2]);
                    accA[k4*4+3] = fmaf(pa, vv.w, accA[k4*4+3]);
                    accB[k4*4+0] = fmaf(pb, vv.x, accB[k4*4+0]);
                    accB[k4*4+1] = fmaf(pb, vv.y, accB[k4*4+1]);
                    accB[k4*4+2] = fmaf(pb, vv.z, accB[k4*4+2]);
                    accB[k4*4+3] = fmaf(pb, vv.w, accB[k4*4+3]);
                }
            }
        }
        float* red = red_s + warp*1056;
        #pragma unroll
        for (int d = 0; d < 32; d++) red[lane*33 + d] = accA[d];
        __syncwarp();
        float totA = 0.f;
        #pragma unroll
        for (int L = 0; L < 32; L++) totA += red[L*33 + lane];
        if (aA) g_attout[((size_t)b*NN + iA)*CC + h*DD + lane] = totA * invA;
        __syncwarp();
        #pragma unroll
        for (int d = 0; d < 32; d++) red[lane*33 + d] = accB[d];
        __syncwarp();
        float totB = 0.f;
        #pragma unroll
        for (int L = 0; L < 32; L++) totB += red[L*33 + lane];
        if (aB) g_attout[((size_t)b*NN + iB)*CC + h*DD + lane] = totB * invB;
        __syncwarp();
    }
}

// ---------------------------------------------------------------------------
extern "C" void kernel_launch(void* const* d_in, const int* in_sizes, int n_in,
                              void* d_out, int out_size) {
    const float* skip   = (const float*)d_in[0];
    const float* x_up   = (const float*)d_in[1];
    const float* pos    = (const float*)d_in[2];
    const float* mask   = (const float*)d_in[3];
    const float* kv_w   = (const float*)d_in[4];
    const float* kv_b   = (const float*)d_in[5];
    const float* proj_w = (const float*)d_in[6];
    const float* proj_b = (const float*)d_in[7];
    const float* lscale = (const float*)d_in[8];
    const float* rpb    = (const float*)d_in[9];
    float* out = (float*)d_out;

    __nv_bfloat16 *skip_hi, *skip_lo, *ain_hi, *ain_lo, *kvw_hi, *kvw_lo, *pw_hi, *pw_lo;
    cudaGetSymbolAddress((void**)&skip_hi, g_skip_hi);
    cudaGetSymbolAddress((void**)&skip_lo, g_skip_lo);
    cudaGetSymbolAddress((void**)&ain_hi,  g_ain_hi);
    cudaGetSymbolAddress((void**)&ain_lo,  g_ain_lo);
    cudaGetSymbolAddress((void**)&kvw_hi,  g_kvw_hi);
    cudaGetSymbolAddress((void**)&kvw_lo,  g_kvw_lo);
    cudaGetSymbolAddress((void**)&pw_hi,   g_pw_hi);
    cudaGetSymbolAddress((void**)&pw_lo,   g_pw_lo);
    float* attout;
    cudaGetSymbolAddress((void**)&attout, g_attout);

    cudaFuncSetAttribute(attn_kernel,
                         cudaFuncAttributeMaxDynamicSharedMemorySize, ATTN_SMEM_BYTES);
    cudaFuncSetAttribute(kv_gemm_mma,
                         cudaFuncAttributeMaxDynamicSharedMemorySize, GEMM_SMEM);
    cudaFuncSetAttribute(proj_gemm_mma,
                         cudaFuncAttributeMaxDynamicSharedMemorySize, GEMM_SMEM);

    // prep: bf16 hi/lo splits
    prep_split<<<131712, 256>>>(skip, skip_hi, skip_lo);
    prep_w_split<<<NKV*CC/256, 256>>>(kv_w, NKV, kvw_hi, kvw_lo);
    prep_w_split<<<CC*CC/256, 256>>>(proj_w, CC, pw_hi, pw_lo);
    // q normalize
    qnorm_kernel<<<131712, 256>>>(x_up, lscale);
    // kv GEMM (HMMA mma.sync, 3x-bf16) + scatter
    kv_gemm_mma<<<dim3(NKV/128, MROWS/128), 256, GEMM_SMEM>>>(kv_b);
    // k normalize
    knorm_kernel<<<131712, 256>>>();
    // attention
    attn_kernel<<<B_*HH, 256, ATTN_SMEM_BYTES>>>(mask, rpb);
    // proj input = attout + pos, split
    prep_add_split<<<131712, 256>>>(attout, pos, ain_hi, ain_lo);
    // proj GEMM (HMMA mma.sync, 3x-bf16)
    proj_gemm_mma<<<dim3(CC/128, MROWS/128), 256, GEMM_SMEM>>>(proj_b, out);
}